// round 17
// baseline (speedup 1.0000x reference)
#include <cuda_runtime.h>
#include <cstdint>

// Shapes (fixed by the problem)
#define S_IN   2048
#define S_T    2048
#define BATCH  8
#define HID    64

#define TM      16           // t-rows per CTA
#define THREADS 256          // 8 warps; warp w owns cols {j*64 + w*8 .. +7}, j=0..31
#define NJ      32
#define NCT     256          // col-tiles of 8 s-cols
#define SSP     2056         // sS pitch (floats)
#define LPITCH  68           // sWT staging pitch

// Fragment-layout scratch: [b][ct][split][lane][20 floats] (80 B records)
// record: floats[4q..4q+3] = {kk=2q:b0, kk=2q:b1, kk=2q+1:b0, kk=2q+1:b1}
__device__ float g_frag[BATCH][NCT][2][32][20];

// SMEM (floats): sS[16][SSP] | sP[16][64] | stage[8 warps][2 bufs][2 splits][32][20]
#define SS_FLOATS   (TM * SSP)
#define SP_OFF      SS_FLOATS
#define STAGE_OFF   (SP_OFF + TM * HID)
#define SLOT_F      (2 * 32 * 20)          // per-buffer floats (hi+lo)
#define SMEM_FLOATS (STAGE_OFF + 8 * 2 * SLOT_F)

__device__ __forceinline__ float tf32_hi(float x) {
    uint32_t u;
    asm("cvt.rna.tf32.f32 %0, %1;" : "=r"(u) : "f"(x));
    return __uint_as_float(u);
}
__device__ __forceinline__ uint32_t smem_u32_of(const void* p) {
    uint32_t a;
    asm("{ .reg .u64 t; cvta.to.shared.u64 t, %1; cvt.u32.u64 %0, t; }" : "=r"(a) : "l"(p));
    return a;
}
__device__ __forceinline__ void cp16(uint32_t dst, const void* src) {
    asm volatile("cp.async.cg.shared.global [%0], [%1], 16;" :: "r"(dst), "l"(src) : "memory");
}
__device__ __forceinline__ void cp_commit() { asm volatile("cp.async.commit_group;" ::: "memory"); }
__device__ __forceinline__ void cp_wait1()  { asm volatile("cp.async.wait_group 1;" ::: "memory"); }
__device__ __forceinline__ void cp_wait0()  { asm volatile("cp.async.wait_group 0;" ::: "memory"); }

// D = A(16x8,row) * B(8x8,col) + D, tf32 inputs, f32 accum
__device__ __forceinline__ void mma8(float c[4], const float a[4], float b0, float b1) {
    asm volatile(
        "mma.sync.aligned.m16n8k8.row.col.f32.tf32.tf32.f32 "
        "{%0,%1,%2,%3}, {%4,%5,%6,%7}, {%8,%9}, {%0,%1,%2,%3};"
        : "+f"(c[0]), "+f"(c[1]), "+f"(c[2]), "+f"(c[3])
        : "r"(__float_as_uint(a[0])), "r"(__float_as_uint(a[1])),
          "r"(__float_as_uint(a[2])), "r"(__float_as_uint(a[3])),
          "r"(__float_as_uint(b0)),  "r"(__float_as_uint(b1)));
}

__device__ __forceinline__ float warp_sum(float v) {
    v += __shfl_xor_sync(0xffffffffu, v, 16);
    v += __shfl_xor_sync(0xffffffffu, v, 8);
    v += __shfl_xor_sync(0xffffffffu, v, 4);
    v += __shfl_xor_sync(0xffffffffu, v, 2);
    v += __shfl_xor_sync(0xffffffffu, v, 1);
    return v;
}
__device__ __forceinline__ float warp_max(float v) {
    v = fmaxf(v, __shfl_xor_sync(0xffffffffu, v, 16));
    v = fmaxf(v, __shfl_xor_sync(0xffffffffu, v, 8));
    v = fmaxf(v, __shfl_xor_sync(0xffffffffu, v, 4));
    v = fmaxf(v, __shfl_xor_sync(0xffffffffu, v, 2));
    v = fmaxf(v, __shfl_xor_sync(0xffffffffu, v, 1));
    return v;
}

// ---------------- pre-kernel: split input into fragment-layout hi/lo ---------
__global__ void __launch_bounds__(256, 2)
split_kernel(const float* __restrict__ inp)
{
    const int idx = blockIdx.x * 256 + threadIdx.x;   // 65536 records
    const int l  = idx & 31;
    const int ct = (idx >> 5) & 255;
    const int b  = idx >> 13;

    const int s = ct * 8 + (l >> 2);
    const float* src = inp + ((size_t)(s * BATCH + b)) * HID;
    float hi[16], lo[16];
    #pragma unroll
    for (int kk = 0; kk < 8; ++kk) {
        #pragma unroll
        for (int t = 0; t < 2; ++t) {
            const int h = kk * 8 + (l & 3) + t * 4;
            const float x = src[h];
            const float hf = tf32_hi(x);
            hi[kk * 2 + t] = hf;
            lo[kk * 2 + t] = x - hf;
        }
    }
    float* dh = &g_frag[b][ct][0][l][0];
    float* dl = &g_frag[b][ct][1][l][0];
    #pragma unroll
    for (int q = 0; q < 4; ++q) {
        *reinterpret_cast<float4*>(dh + 4 * q) = make_float4(hi[4*q], hi[4*q+1], hi[4*q+2], hi[4*q+3]);
        *reinterpret_cast<float4*>(dl + 4 * q) = make_float4(lo[4*q], lo[4*q+1], lo[4*q+2], lo[4*q+3]);
    }
}

__global__ void __launch_bounds__(THREADS, 1)
attn_mma_kernel(const float* __restrict__ inp,        // (S_IN, B, H) (unused here)
                const float* __restrict__ tgt,        // (S_T, B, H)
                const unsigned char* __restrict__ msk,// (B, S_T, S_IN) bool
                const float* __restrict__ Wm,         // (H, H)  W[o][h]
                const float* __restrict__ bias,       // (H)
                float* __restrict__ out)              // (B, S_T, S_IN)
{
    extern __shared__ float sm[];
    float* sS = sm;                     // scores, pitch SSP
    float* sP = sm + SP_OFF;            // P = tgt_tile @ W^T + b, [16][64]
    float* sStage = sm + STAGE_OFF;     // per-warp double-buffered frag slots

    const int tid  = threadIdx.x;
    const int w    = tid >> 5;
    const int l    = tid & 31;
    const int b    = blockIdx.x >> 7;
    const int t0   = (blockIdx.x & 127) << 4;

    // ---------------- linear stage: P = tgt_tile @ W^T + bias -----------------
    {
        float* sWT = sS;                 // [64][LPITCH]
        float* sTg = sS + HID * LPITCH;  // [16][64]
        const int o  = tid >> 2;
        const int hq = (tid & 3) * 16;
        #pragma unroll
        for (int k = 0; k < 4; ++k) {
            float4 wv = *reinterpret_cast<const float4*>(Wm + o * HID + hq + 4 * k);
            sWT[(hq + 4 * k + 0) * LPITCH + o] = wv.x;
            sWT[(hq + 4 * k + 1) * LPITCH + o] = wv.y;
            sWT[(hq + 4 * k + 2) * LPITCH + o] = wv.z;
            sWT[(hq + 4 * k + 3) * LPITCH + o] = wv.w;
        }
        const int r  = tid >> 4;
        const int hh = (tid & 15) * 4;
        *reinterpret_cast<float4*>(sTg + r * HID + hh) =
            *reinterpret_cast<const float4*>(tgt + ((size_t)((t0 + r) * BATCH + b)) * HID + hh);
        __syncthreads();

        const int o0 = (tid & 15) * 4;
        float4 acc = *reinterpret_cast<const float4*>(bias + o0);
        #pragma unroll
        for (int h = 0; h < HID; ++h) {
            const float  tv = sTg[r * HID + h];
            const float4 wv = *reinterpret_cast<const float4*>(sWT + h * LPITCH + o0);
            acc.x += tv * wv.x;
            acc.y += tv * wv.y;
            acc.z += tv * wv.z;
            acc.w += tv * wv.w;
        }
        *reinterpret_cast<float4*>(sP + r * HID + o0) = acc;
        __syncthreads();   // P visible; sS region free for scores
    }

    // ---------------- preload A fragments (hi/lo tf32 split) ------------------
    float ah[8][4], al[8][4];
    {
        const float* p0 = sP + (l >> 2) * HID;
        const float* p1 = p0 + 8 * HID;
        #pragma unroll
        for (int kk = 0; kk < 8; ++kk) {
            const int k0 = kk * 8 + (l & 3);
            const float a0 = p0[k0], a1 = p1[k0], a2 = p0[k0 + 4], a3 = p1[k0 + 4];
            ah[kk][0] = tf32_hi(a0); al[kk][0] = a0 - ah[kk][0];
            ah[kk][1] = tf32_hi(a1); al[kk][1] = a1 - ah[kk][1];
            ah[kk][2] = tf32_hi(a2); al[kk][2] = a2 - ah[kk][2];
            ah[kk][3] = tf32_hi(a3); al[kk][3] = a3 - ah[kk][3];
        }
    }

    // ---------------- score GEMM: 32 tiles of 8 s-cols per warp ---------------
    // Pre-split fragments streamed via cp.async; no per-tile ALU.
    float* slotBase = sStage + w * (2 * SLOT_F);
    const uint32_t slotU0 = smem_u32_of(slotBase);
    const uint32_t laneB  = (uint32_t)(l * 80);         // lane record byte offset
    const float* gbaseF = &g_frag[b][0][0][0][0];

    // prologue: issue tile 0 (ct = w) into buf 0
    {
        const float* srcH = gbaseF + ((size_t)w * 2 + 0) * (32 * 20) + l * 20;
        const float* srcL = gbaseF + ((size_t)w * 2 + 1) * (32 * 20) + l * 20;
        #pragma unroll
        for (int q = 0; q < 4; ++q) {
            cp16(slotU0 + laneB + 16 * q,        srcH + 4 * q);
            cp16(slotU0 + 2560 + laneB + 16 * q, srcL + 4 * q);
        }
        cp_commit();
    }

    #pragma unroll 4
    for (int j = 0; j < NJ; ++j) {
        const int buf = j & 1;
        if (j + 1 < NJ) {                 // issue next tile into the other buffer
            const int ct = (j + 1) * 8 + w;
            const float* srcH = gbaseF + ((size_t)ct * 2 + 0) * (32 * 20) + l * 20;
            const float* srcL = gbaseF + ((size_t)ct * 2 + 1) * (32 * 20) + l * 20;
            const uint32_t dst = slotU0 + (uint32_t)((buf ^ 1) * SLOT_F * 4) + laneB;
            #pragma unroll
            for (int q = 0; q < 4; ++q) {
                cp16(dst + 16 * q,        srcH + 4 * q);
                cp16(dst + 2560 + 16 * q, srcL + 4 * q);
            }
            cp_commit();
            cp_wait1();                   // tile j's group complete (j+1 in flight)
        } else {
            cp_wait0();
        }
        __syncwarp();                     // all lanes' copies of tile j visible

        // fragment loads: 4+4 LDS.128, zero ALU before MMA
        const float* fb = slotBase + buf * SLOT_F + l * 20;
        float4 hv[4], lv[4];
        #pragma unroll
        for (int q = 0; q < 4; ++q) {
            hv[q] = *reinterpret_cast<const float4*>(fb + 4 * q);
            lv[q] = *reinterpret_cast<const float4*>(fb + 640 + 4 * q);
        }

        // 3 independent accumulator chains, interleaved
        float chh[4] = {0.f, 0.f, 0.f, 0.f};
        float clh[4] = {0.f, 0.f, 0.f, 0.f};
        float chl[4] = {0.f, 0.f, 0.f, 0.f};
        #pragma unroll
        for (int q = 0; q < 4; ++q) {
            mma8(chh, ah[2*q],   hv[q].x, hv[q].y);
            mma8(clh, al[2*q],   hv[q].x, hv[q].y);
            mma8(chl, ah[2*q],   lv[q].x, lv[q].y);
            mma8(chh, ah[2*q+1], hv[q].z, hv[q].w);
            mma8(clh, al[2*q+1], hv[q].z, hv[q].w);
            mma8(chl, ah[2*q+1], lv[q].z, lv[q].w);
        }

        // combine + store: c0,c1 -> row l/4; c2,c3 -> row l/4+8
        const float c0 = chh[0] + clh[0] + chl[0];
        const float c1 = chh[1] + clh[1] + chl[1];
        const float c2 = chh[2] + clh[2] + chl[2];
        const float c3 = chh[3] + clh[3] + chl[3];
        float* dst = sS + (l >> 2) * SSP + j * 64 + w * 8 + 2 * (l & 3);
        *reinterpret_cast<float2*>(dst)            = make_float2(c0, c1);
        *reinterpret_cast<float2*>(dst + 8 * SSP)  = make_float2(c2, c3);
    }
    __syncthreads();

    // ---------------- register-resident epilogue: warp w -> rows 2w, 2w+1 -----
    const float NEG_INF = __int_as_float(0xff800000);
    #pragma unroll
    for (int rr = 0; rr < 2; ++rr) {
        const int r = w * 2 + rr;
        const float* row = sS + r * SSP;
        const size_t gbase = ((size_t)(b * S_T + (t0 + r))) * S_IN;

        float4 v[16];
        float s = 0.f;
        #pragma unroll
        for (int i = 0; i < 16; ++i) {
            v[i] = *reinterpret_cast<const float4*>(row + i * 128 + l * 4);
            s += (v[i].x + v[i].y) + (v[i].z + v[i].w);
        }
        s = warp_sum(s);
        const float mean = s * (1.0f / 2048.0f);

        float m = NEG_INF;
        #pragma unroll
        for (int i = 0; i < 16; ++i) {
            const unsigned int mk = *reinterpret_cast<const unsigned int*>(
                msk + gbase + i * 128 + l * 4);
            v[i].x = fabsf(v[i].x - mean);
            v[i].y = fabsf(v[i].y - mean);
            v[i].z = fabsf(v[i].z - mean);
            v[i].w = fabsf(v[i].w - mean);
            if (mk & 0x000000FFu) v[i].x = NEG_INF;
            if (mk & 0x0000FF00u) v[i].y = NEG_INF;
            if (mk & 0x00FF0000u) v[i].z = NEG_INF;
            if (mk & 0xFF000000u) v[i].w = NEG_INF;
            m = fmaxf(m, fmaxf(fmaxf(v[i].x, v[i].y), fmaxf(v[i].z, v[i].w)));
        }
        m = warp_max(m);

        float lsum = 0.f;
        #pragma unroll
        for (int i = 0; i < 16; ++i) {
            v[i].x = __expf(v[i].x - m);
            v[i].y = __expf(v[i].y - m);
            v[i].z = __expf(v[i].z - m);
            v[i].w = __expf(v[i].w - m);
            lsum += (v[i].x + v[i].y) + (v[i].z + v[i].w);
        }
        lsum = warp_sum(lsum);
        const float inv = 1.0f / lsum;

        #pragma unroll
        for (int i = 0; i < 16; ++i) {
            v[i].x *= inv; v[i].y *= inv; v[i].z *= inv; v[i].w *= inv;
            *reinterpret_cast<float4*>(out + gbase + i * 128 + l * 4) = v[i];
        }
    }
}

extern "C" void kernel_launch(void* const* d_in, const int* in_sizes, int n_in,
                              void* d_out, int out_size)
{
    const float*         inp  = (const float*)d_in[0];
    const float*         tgt  = (const float*)d_in[1];
    const unsigned char* msk  = (const unsigned char*)d_in[2];
    const float*         Wm   = (const float*)d_in[3];
    const float*         bias = (const float*)d_in[4];
    float*               out  = (float*)d_out;

    const int smem_bytes = SMEM_FLOATS * (int)sizeof(float); // ~218 KB
    cudaFuncSetAttribute(attn_mma_kernel,
                         cudaFuncAttributeMaxDynamicSharedMemorySize, smem_bytes);

    split_kernel<<<256, 256>>>(inp);                 // fill g_frag (hi/lo frags)

    dim3 grid(BATCH * (S_T / TM));  // 1024 CTAs
    dim3 block(THREADS);
    attn_mma_kernel<<<grid, block, smem_bytes>>>(inp, tgt, msk, Wm, bias, out);
}